// round 12
// baseline (speedup 1.0000x reference)
#include <cuda_runtime.h>
#include <cuda_bf16.h>
#include <cstdint>

#define N_NODES 65536
#define N_EDGES 1048576
#define IN_F 64
#define OUT_F 64

// ---- scratch (static __device__, 16B-aligned, no allocation) ----
__device__ __align__(16) float g_support[(size_t)N_NODES * OUT_F];  // 16 MB
__device__ __align__(16) uint2 g_sorted[N_EDGES];                   // 8 MB
__device__ __align__(16) int   g_counts[N_NODES];
__device__ __align__(16) int   g_rowptr[N_NODES];
__device__ __align__(16) int   g_cursor[N_NODES];

// ---------------------------------------------------------------------------
// support = X @ W   (one thread per row, W broadcast from smem)
// ---------------------------------------------------------------------------
__global__ void __launch_bounds__(256)
gemm_kernel(const float* __restrict__ X, const float* __restrict__ W,
            float* __restrict__ S, int n_nodes)
{
    __shared__ float sW[IN_F * OUT_F];
    for (int i = threadIdx.x; i < IN_F * OUT_F; i += 256)
        sW[i] = W[i];
    __syncthreads();

    int row = blockIdx.x * 256 + threadIdx.x;
    if (row >= n_nodes) return;

    float acc[OUT_F];
#pragma unroll
    for (int j = 0; j < OUT_F; j++) acc[j] = 0.0f;

    const float4* xr = reinterpret_cast<const float4*>(X + (size_t)row * IN_F);
#pragma unroll 4
    for (int k4 = 0; k4 < IN_F / 4; k4++) {
        float4 x = xr[k4];
        int k = k4 * 4;
        const float4* w0 = reinterpret_cast<const float4*>(sW + (k + 0) * OUT_F);
        const float4* w1 = reinterpret_cast<const float4*>(sW + (k + 1) * OUT_F);
        const float4* w2 = reinterpret_cast<const float4*>(sW + (k + 2) * OUT_F);
        const float4* w3 = reinterpret_cast<const float4*>(sW + (k + 3) * OUT_F);
#pragma unroll
        for (int j4 = 0; j4 < OUT_F / 4; j4++) {
            float4 a = w0[j4], b = w1[j4], c = w2[j4], d = w3[j4];
            acc[j4 * 4 + 0] += x.x * a.x + x.y * b.x + x.z * c.x + x.w * d.x;
            acc[j4 * 4 + 1] += x.x * a.y + x.y * b.y + x.z * c.y + x.w * d.y;
            acc[j4 * 4 + 2] += x.x * a.z + x.y * b.z + x.z * c.z + x.w * d.z;
            acc[j4 * 4 + 3] += x.x * a.w + x.y * b.w + x.z * c.w + x.w * d.w;
        }
    }

    float4* sr = reinterpret_cast<float4*>(S + (size_t)row * OUT_F);
#pragma unroll
    for (int j4 = 0; j4 < OUT_F / 4; j4++)
        sr[j4] = make_float4(acc[j4*4+0], acc[j4*4+1], acc[j4*4+2], acc[j4*4+3]);
}

// ---------------------------------------------------------------------------
// zero degree counters
// ---------------------------------------------------------------------------
__global__ void __launch_bounds__(256)
zero_counts_kernel(int* __restrict__ counts, int n)
{
    int i = blockIdx.x * 256 + threadIdx.x;
    if (i < n) counts[i] = 0;
}

// ---------------------------------------------------------------------------
// histogram of destination rows (R7-proven version, no rank output)
// ---------------------------------------------------------------------------
__global__ void __launch_bounds__(256)
hist_kernel(const int* __restrict__ rows, int* __restrict__ counts, int n_edges)
{
    int e = blockIdx.x * 256 + threadIdx.x;
    if (e < n_edges) atomicAdd(&counts[rows[e]], 1);
}

// ---------------------------------------------------------------------------
// exclusive prefix sum over 65536 counts (single block, vectorized;
// R7-proven version writing rowptr AND cursor)
// ---------------------------------------------------------------------------
__global__ void __launch_bounds__(1024)
scan_kernel(const int* __restrict__ counts, int* __restrict__ rowptr,
            int* __restrict__ cursor, int n)
{
    __shared__ int ssum[1024];
    int t = threadIdx.x;
    int base = t * 64;

    int4 c[16];
    const int4* cp = reinterpret_cast<const int4*>(counts + base);
#pragma unroll
    for (int i = 0; i < 16; i++) c[i] = cp[i];

    int chunk = 0;
#pragma unroll
    for (int i = 0; i < 16; i++) chunk += c[i].x + c[i].y + c[i].z + c[i].w;
    ssum[t] = chunk;
    __syncthreads();

    for (int d = 1; d < 1024; d <<= 1) {
        int add = (t >= d) ? ssum[t - d] : 0;
        __syncthreads();
        ssum[t] += add;
        __syncthreads();
    }
    int run = ssum[t] - chunk;

    int4* rp = reinterpret_cast<int4*>(rowptr + base);
    int4* up = reinterpret_cast<int4*>(cursor + base);
#pragma unroll
    for (int i = 0; i < 16; i++) {
        int4 o;
        o.x = run; run += c[i].x;
        o.y = run; run += c[i].y;
        o.z = run; run += c[i].z;
        o.w = run; run += c[i].w;
        rp[i] = o;
        up[i] = o;
    }
}

// ---------------------------------------------------------------------------
// place each edge into its dest bucket (R7-proven cursor-atomic version)
// ---------------------------------------------------------------------------
__global__ void __launch_bounds__(256)
place_kernel(const int* __restrict__ rows, const int* __restrict__ cols,
             const float* __restrict__ vals, int* __restrict__ cursor,
             uint2* __restrict__ sorted, int n_edges)
{
    int e = blockIdx.x * 256 + threadIdx.x;
    if (e >= n_edges) return;
    int r = rows[e];
    int pos = atomicAdd(&cursor[r], 1);
    sorted[pos] = make_uint2((unsigned)cols[e], __float_as_uint(vals[e]));
}

// ---------------------------------------------------------------------------
// Gather v3 (hardened): ONE WARP PER NODE. Lane owns one float2
// (32 lanes = 256B row). Edge loads are warp-uniform; batches of 4 with
// next-batch prefetch. ALL indices are clamped/masked by construction:
//   - gathered col masked with N_NODES-1 (power of two)
//   - start/deg clamped so ep[0..deg) stays inside sorted[]
// Single non-atomic write of relu(acc + bias) per lane.
// ---------------------------------------------------------------------------
__global__ void __launch_bounds__(256)
gather_kernel(const int* __restrict__ rowptr, const int* __restrict__ counts,
              const uint2* __restrict__ sorted, const float* __restrict__ S,
              const float* __restrict__ bias, float* __restrict__ out,
              int n_nodes)
{
    int node = (blockIdx.x * 256 + threadIdx.x) >> 5;
    if (node >= n_nodes) return;
    int lane = threadIdx.x & 31;

    int start = rowptr[node];
    int deg   = counts[node];

    // defensive clamps: gather can never read outside sorted[] / S[]
    if (start < 0) start = 0;
    if (start > N_EDGES) start = N_EDGES;
    if (deg < 0) deg = 0;
    if (deg > N_EDGES - start) deg = N_EDGES - start;

    const uint2*  ep = sorted + start;
    const float2* S2 = reinterpret_cast<const float2*>(S);

    float2 acc = make_float2(0.f, 0.f);
    int nb = (deg + 3) >> 2;

    uint2 a0 = (0 < deg) ? ep[0] : make_uint2(0u, 0u);
    uint2 a1 = (1 < deg) ? ep[1] : make_uint2(0u, 0u);
    uint2 a2 = (2 < deg) ? ep[2] : make_uint2(0u, 0u);
    uint2 a3 = (3 < deg) ? ep[3] : make_uint2(0u, 0u);

    for (int b = 0; b < nb; b++) {
        float2 s0 = S2[(size_t)(a0.x & (N_NODES - 1)) * 32 + lane];
        float2 s1 = S2[(size_t)(a1.x & (N_NODES - 1)) * 32 + lane];
        float2 s2 = S2[(size_t)(a2.x & (N_NODES - 1)) * 32 + lane];
        float2 s3 = S2[(size_t)(a3.x & (N_NODES - 1)) * 32 + lane];

        int nxt = (b + 1) * 4;
        uint2 b0 = (nxt + 0 < deg) ? ep[nxt + 0] : make_uint2(0u, 0u);
        uint2 b1 = (nxt + 1 < deg) ? ep[nxt + 1] : make_uint2(0u, 0u);
        uint2 b2 = (nxt + 2 < deg) ? ep[nxt + 2] : make_uint2(0u, 0u);
        uint2 b3 = (nxt + 3 < deg) ? ep[nxt + 3] : make_uint2(0u, 0u);

        float v0 = __uint_as_float(a0.y);
        float v1 = __uint_as_float(a1.y);
        float v2 = __uint_as_float(a2.y);
        float v3 = __uint_as_float(a3.y);
        acc.x += v0 * s0.x; acc.y += v0 * s0.y;
        acc.x += v1 * s1.x; acc.y += v1 * s1.y;
        acc.x += v2 * s2.x; acc.y += v2 * s2.y;
        acc.x += v3 * s3.x; acc.y += v3 * s3.y;

        a0 = b0; a1 = b1; a2 = b2; a3 = b3;
    }

    float2 bb = reinterpret_cast<const float2*>(bias)[lane];
    float2 r;
    r.x = fmaxf(acc.x + bb.x, 0.f);
    r.y = fmaxf(acc.y + bb.y, 0.f);
    reinterpret_cast<float2*>(out)[(size_t)node * 32 + lane] = r;
}

extern "C" void kernel_launch(void* const* d_in, const int* in_sizes, int n_in,
                              void* d_out, int out_size)
{
    const float* X    = (const float*)d_in[0];
    const int*   rows = (const int*)  d_in[1];
    const int*   cols = (const int*)  d_in[2];
    const float* vals = (const float*)d_in[3];
    const float* W    = (const float*)d_in[4];
    const float* bias = (const float*)d_in[5];
    float*       out  = (float*)d_out;

    int n_nodes = in_sizes[0] / IN_F;
    int n_edges = in_sizes[1];

    float* S;      cudaGetSymbolAddress((void**)&S,      g_support);
    uint2* sorted; cudaGetSymbolAddress((void**)&sorted, g_sorted);
    int*   counts; cudaGetSymbolAddress((void**)&counts, g_counts);
    int*   rowptr; cudaGetSymbolAddress((void**)&rowptr, g_rowptr);
    int*   cursor; cudaGetSymbolAddress((void**)&cursor, g_cursor);

    // Single stream, strictly ordered (R7-proven CSR build).
    gemm_kernel<<<(n_nodes + 255) / 256, 256>>>(X, W, S, n_nodes);
    zero_counts_kernel<<<(n_nodes + 255) / 256, 256>>>(counts, n_nodes);
    hist_kernel<<<(n_edges + 255) / 256, 256>>>(rows, counts, n_edges);
    scan_kernel<<<1, 1024>>>(counts, rowptr, cursor, n_nodes);
    place_kernel<<<(n_edges + 255) / 256, 256>>>(rows, cols, vals, cursor,
                                                 sorted, n_edges);

    long long total = (long long)n_nodes * 32;
    gather_kernel<<<(int)((total + 255) / 256), 256>>>(rowptr, counts, sorted,
                                                       S, bias, out, n_nodes);
}

// round 13
// speedup vs baseline: 1.4990x; 1.4990x over previous
#include <cuda_runtime.h>
#include <cuda_bf16.h>
#include <cstdint>

#define N_NODES 65536
#define N_EDGES 1048576
#define IN_F 64
#define OUT_F 64

#define SCAN_BLOCKS 64          // 64 blocks x 256 threads x 4 counts = 65536

// ---- scratch (static __device__, 16B-aligned, no allocation) ----
__device__ __align__(16) float g_support[(size_t)N_NODES * OUT_F];  // 16 MB
__device__ __align__(16) uint2 g_sorted[N_EDGES];                   // 8 MB
__device__ __align__(16) int   g_counts[N_NODES];
__device__ __align__(16) int   g_rowptr[N_NODES];
__device__ __align__(16) int   g_cursor[N_NODES];
__device__ __align__(16) int   g_blocksums[SCAN_BLOCKS];
__device__ __align__(16) int   g_blockoffs[SCAN_BLOCKS];

// ---------------------------------------------------------------------------
// support = X @ W   (one thread per row, W broadcast from smem)
// ---------------------------------------------------------------------------
__global__ void __launch_bounds__(256)
gemm_kernel(const float* __restrict__ X, const float* __restrict__ W,
            float* __restrict__ S, int n_nodes)
{
    __shared__ float sW[IN_F * OUT_F];
    for (int i = threadIdx.x; i < IN_F * OUT_F; i += 256)
        sW[i] = W[i];
    __syncthreads();

    int row = blockIdx.x * 256 + threadIdx.x;
    if (row >= n_nodes) return;

    float acc[OUT_F];
#pragma unroll
    for (int j = 0; j < OUT_F; j++) acc[j] = 0.0f;

    const float4* xr = reinterpret_cast<const float4*>(X + (size_t)row * IN_F);
#pragma unroll 4
    for (int k4 = 0; k4 < IN_F / 4; k4++) {
        float4 x = xr[k4];
        int k = k4 * 4;
        const float4* w0 = reinterpret_cast<const float4*>(sW + (k + 0) * OUT_F);
        const float4* w1 = reinterpret_cast<const float4*>(sW + (k + 1) * OUT_F);
        const float4* w2 = reinterpret_cast<const float4*>(sW + (k + 2) * OUT_F);
        const float4* w3 = reinterpret_cast<const float4*>(sW + (k + 3) * OUT_F);
#pragma unroll
        for (int j4 = 0; j4 < OUT_F / 4; j4++) {
            float4 a = w0[j4], b = w1[j4], c = w2[j4], d = w3[j4];
            acc[j4 * 4 + 0] += x.x * a.x + x.y * b.x + x.z * c.x + x.w * d.x;
            acc[j4 * 4 + 1] += x.x * a.y + x.y * b.y + x.z * c.y + x.w * d.y;
            acc[j4 * 4 + 2] += x.x * a.z + x.y * b.z + x.z * c.z + x.w * d.z;
            acc[j4 * 4 + 3] += x.x * a.w + x.y * b.w + x.z * c.w + x.w * d.w;
        }
    }

    float4* sr = reinterpret_cast<float4*>(S + (size_t)row * OUT_F);
#pragma unroll
    for (int j4 = 0; j4 < OUT_F / 4; j4++)
        sr[j4] = make_float4(acc[j4*4+0], acc[j4*4+1], acc[j4*4+2], acc[j4*4+3]);
}

// ---------------------------------------------------------------------------
// zero degree counters
// ---------------------------------------------------------------------------
__global__ void __launch_bounds__(256)
zero_counts_kernel(int* __restrict__ counts, int n)
{
    int i = blockIdx.x * 256 + threadIdx.x;
    if (i < n) counts[i] = 0;
}

// ---------------------------------------------------------------------------
// histogram of destination rows
// ---------------------------------------------------------------------------
__global__ void __launch_bounds__(256)
hist_kernel(const int* __restrict__ rows, int* __restrict__ counts, int n_edges)
{
    int e = blockIdx.x * 256 + threadIdx.x;
    if (e < n_edges) atomicAdd(&counts[rows[e]], 1);
}

// ---------------------------------------------------------------------------
// scan phase A: 64 blocks; each reduces its 1024 counts to one block sum
// ---------------------------------------------------------------------------
__global__ void __launch_bounds__(256)
scan_a_kernel(const int* __restrict__ counts, int* __restrict__ blocksums)
{
    __shared__ int sred[256];
    int t = threadIdx.x;
    int4 c = reinterpret_cast<const int4*>(counts)[blockIdx.x * 256 + t];
    int s = c.x + c.y + c.z + c.w;
    sred[t] = s;
    __syncthreads();
    for (int d = 128; d > 0; d >>= 1) {
        if (t < d) sred[t] += sred[t + d];
        __syncthreads();
    }
    if (t == 0) blocksums[blockIdx.x] = sred[0];
}

// ---------------------------------------------------------------------------
// scan phase B: one tiny block scans the 64 block sums (exclusive)
// ---------------------------------------------------------------------------
__global__ void __launch_bounds__(64)
scan_b_kernel(const int* __restrict__ blocksums, int* __restrict__ blockoffs)
{
    __shared__ int s[64];
    int t = threadIdx.x;
    int v = blocksums[t];
    s[t] = v;
    __syncthreads();
    for (int d = 1; d < 64; d <<= 1) {
        int add = (t >= d) ? s[t - d] : 0;
        __syncthreads();
        s[t] += add;
        __syncthreads();
    }
    blockoffs[t] = s[t] - v;   // exclusive
}

// ---------------------------------------------------------------------------
// scan phase C: 64 blocks; block-local exclusive scan + global block offset,
// emits rowptr and cursor.
// ---------------------------------------------------------------------------
__global__ void __launch_bounds__(256)
scan_c_kernel(const int* __restrict__ counts, const int* __restrict__ blockoffs,
              int* __restrict__ rowptr, int* __restrict__ cursor)
{
    __shared__ int ssum[256];
    int t = threadIdx.x;
    int gidx = blockIdx.x * 256 + t;

    int4 c = reinterpret_cast<const int4*>(counts)[gidx];
    int s = c.x + c.y + c.z + c.w;
    ssum[t] = s;
    __syncthreads();
    for (int d = 1; d < 256; d <<= 1) {
        int add = (t >= d) ? ssum[t - d] : 0;
        __syncthreads();
        ssum[t] += add;
        __syncthreads();
    }
    int run = blockoffs[blockIdx.x] + ssum[t] - s;  // exclusive prefix

    int4 o;
    o.x = run; run += c.x;
    o.y = run; run += c.y;
    o.z = run; run += c.z;
    o.w = run; run += c.w;
    reinterpret_cast<int4*>(rowptr)[gidx] = o;
    reinterpret_cast<int4*>(cursor)[gidx] = o;
}

// ---------------------------------------------------------------------------
// place each edge into its dest bucket (cursor-atomic, proven)
// ---------------------------------------------------------------------------
__global__ void __launch_bounds__(256)
place_kernel(const int* __restrict__ rows, const int* __restrict__ cols,
             const float* __restrict__ vals, int* __restrict__ cursor,
             uint2* __restrict__ sorted, int n_edges)
{
    int e = blockIdx.x * 256 + threadIdx.x;
    if (e >= n_edges) return;
    int r = rows[e];
    int pos = atomicAdd(&cursor[r], 1);
    sorted[pos] = make_uint2((unsigned)cols[e], __float_as_uint(vals[e]));
}

// ---------------------------------------------------------------------------
// Gather v3 (hardened, byte-identical to the passing R12 version).
// ---------------------------------------------------------------------------
__global__ void __launch_bounds__(256)
gather_kernel(const int* __restrict__ rowptr, const int* __restrict__ counts,
              const uint2* __restrict__ sorted, const float* __restrict__ S,
              const float* __restrict__ bias, float* __restrict__ out,
              int n_nodes)
{
    int node = (blockIdx.x * 256 + threadIdx.x) >> 5;
    if (node >= n_nodes) return;
    int lane = threadIdx.x & 31;

    int start = rowptr[node];
    int deg   = counts[node];

    if (start < 0) start = 0;
    if (start > N_EDGES) start = N_EDGES;
    if (deg < 0) deg = 0;
    if (deg > N_EDGES - start) deg = N_EDGES - start;

    const uint2*  ep = sorted + start;
    const float2* S2 = reinterpret_cast<const float2*>(S);

    float2 acc = make_float2(0.f, 0.f);
    int nb = (deg + 3) >> 2;

    uint2 a0 = (0 < deg) ? ep[0] : make_uint2(0u, 0u);
    uint2 a1 = (1 < deg) ? ep[1] : make_uint2(0u, 0u);
    uint2 a2 = (2 < deg) ? ep[2] : make_uint2(0u, 0u);
    uint2 a3 = (3 < deg) ? ep[3] : make_uint2(0u, 0u);

    for (int b = 0; b < nb; b++) {
        float2 s0 = S2[(size_t)(a0.x & (N_NODES - 1)) * 32 + lane];
        float2 s1 = S2[(size_t)(a1.x & (N_NODES - 1)) * 32 + lane];
        float2 s2 = S2[(size_t)(a2.x & (N_NODES - 1)) * 32 + lane];
        float2 s3 = S2[(size_t)(a3.x & (N_NODES - 1)) * 32 + lane];

        int nxt = (b + 1) * 4;
        uint2 b0 = (nxt + 0 < deg) ? ep[nxt + 0] : make_uint2(0u, 0u);
        uint2 b1 = (nxt + 1 < deg) ? ep[nxt + 1] : make_uint2(0u, 0u);
        uint2 b2 = (nxt + 2 < deg) ? ep[nxt + 2] : make_uint2(0u, 0u);
        uint2 b3 = (nxt + 3 < deg) ? ep[nxt + 3] : make_uint2(0u, 0u);

        float v0 = __uint_as_float(a0.y);
        float v1 = __uint_as_float(a1.y);
        float v2 = __uint_as_float(a2.y);
        float v3 = __uint_as_float(a3.y);
        acc.x += v0 * s0.x; acc.y += v0 * s0.y;
        acc.x += v1 * s1.x; acc.y += v1 * s1.y;
        acc.x += v2 * s2.x; acc.y += v2 * s2.y;
        acc.x += v3 * s3.x; acc.y += v3 * s3.y;

        a0 = b0; a1 = b1; a2 = b2; a3 = b3;
    }

    float2 bb = reinterpret_cast<const float2*>(bias)[lane];
    float2 r;
    r.x = fmaxf(acc.x + bb.x, 0.f);
    r.y = fmaxf(acc.y + bb.y, 0.f);
    reinterpret_cast<float2*>(out)[(size_t)node * 32 + lane] = r;
}

extern "C" void kernel_launch(void* const* d_in, const int* in_sizes, int n_in,
                              void* d_out, int out_size)
{
    const float* X    = (const float*)d_in[0];
    const int*   rows = (const int*)  d_in[1];
    const int*   cols = (const int*)  d_in[2];
    const float* vals = (const float*)d_in[3];
    const float* W    = (const float*)d_in[4];
    const float* bias = (const float*)d_in[5];
    float*       out  = (float*)d_out;

    int n_nodes = in_sizes[0] / IN_F;
    int n_edges = in_sizes[1];

    float* S;      cudaGetSymbolAddress((void**)&S,      g_support);
    uint2* sorted; cudaGetSymbolAddress((void**)&sorted, g_sorted);
    int*   counts; cudaGetSymbolAddress((void**)&counts, g_counts);
    int*   rowptr; cudaGetSymbolAddress((void**)&rowptr, g_rowptr);
    int*   cursor; cudaGetSymbolAddress((void**)&cursor, g_cursor);
    int*   bsums;  cudaGetSymbolAddress((void**)&bsums,  g_blocksums);
    int*   boffs;  cudaGetSymbolAddress((void**)&boffs,  g_blockoffs);

    // Side stream + events for gemm overlap (capture-legal fork/join).
    static cudaStream_t s_gemm = nullptr;
    static cudaEvent_t  ev_fork = nullptr, ev_done = nullptr;
    if (s_gemm == nullptr) {
        cudaStreamCreateWithFlags(&s_gemm, cudaStreamNonBlocking);
        cudaEventCreateWithFlags(&ev_fork, cudaEventDisableTiming);
        cudaEventCreateWithFlags(&ev_done, cudaEventDisableTiming);
    }

    // Fork: gemm on the side stream, overlapped with the CSR build.
    cudaEventRecord(ev_fork, 0);
    cudaStreamWaitEvent(s_gemm, ev_fork, 0);
    gemm_kernel<<<(n_nodes + 255) / 256, 256, 0, s_gemm>>>(X, W, S, n_nodes);
    cudaEventRecord(ev_done, s_gemm);

    // CSR build on the main stream.
    zero_counts_kernel<<<(n_nodes + 255) / 256, 256>>>(counts, n_nodes);
    hist_kernel<<<(n_edges + 255) / 256, 256>>>(rows, counts, n_edges);
    scan_a_kernel<<<SCAN_BLOCKS, 256>>>(counts, bsums);
    scan_b_kernel<<<1, 64>>>(bsums, boffs);
    scan_c_kernel<<<SCAN_BLOCKS, 256>>>(counts, boffs, rowptr, cursor);
    place_kernel<<<(n_edges + 255) / 256, 256>>>(rows, cols, vals, cursor,
                                                 sorted, n_edges);

    // Join: gather needs both the CSR and the support matrix.
    cudaStreamWaitEvent(0, ev_done, 0);
    long long total = (long long)n_nodes * 32;
    gather_kernel<<<(int)((total + 255) / 256), 256>>>(rowptr, counts, sorted,
                                                       S, bias, out, n_nodes);
}